// round 1
// baseline (speedup 1.0000x reference)
#include <cuda_runtime.h>
#include <cstdint>

#define N_USERS 100000
#define N_ITEMS 150000
#define N_NODES (N_USERS + N_ITEMS)
#define N_EDGES 4000000
#define DIM 64

// Scratch ping-pong buffers for layer embeddings (64 MB each).
__device__ float g_bufA[(size_t)N_NODES * DIM];
__device__ float g_bufB[(size_t)N_NODES * DIM];

// out = concat(user_emb, item_emb); x = same.
__global__ void init_kernel(const float* __restrict__ user_emb,
                            const float* __restrict__ item_emb,
                            float* __restrict__ out,
                            float* __restrict__ x) {
    size_t i = (size_t)blockIdx.x * blockDim.x + threadIdx.x;   // float4 index
    const size_t total4 = (size_t)N_NODES * DIM / 4;
    if (i >= total4) return;
    const size_t ub4 = (size_t)N_USERS * DIM / 4;
    float4 v;
    if (i < ub4) v = ((const float4*)user_emb)[i];
    else         v = ((const float4*)item_emb)[i - ub4];
    ((float4*)out)[i] = v;
    ((float4*)x)[i]   = v;
}

// y[dst] += w * x[src], 16 threads per edge, one v4 red-atomic per thread.
__global__ void __launch_bounds__(256) spmm_kernel(
    const int*   __restrict__ esrc,
    const int*   __restrict__ edst,
    const float* __restrict__ evals,
    const float* __restrict__ x,
    float*       __restrict__ y) {
    size_t t = (size_t)blockIdx.x * blockDim.x + threadIdx.x;
    size_t e = t >> 4;          // edge index
    int    c = (int)(t & 15);   // float4 chunk within the 64-dim row
    if (e >= (size_t)N_EDGES) return;

    int   s = __ldg(esrc + e);
    int   d = __ldg(edst + e);
    float w = __ldg(evals + e);

    float4 v = __ldg(((const float4*)(x + (size_t)s * DIM)) + c);
    float4 m;
    m.x = w * v.x; m.y = w * v.y; m.z = w * v.z; m.w = w * v.w;

    float* p = y + (size_t)d * DIM + (size_t)c * 4;
    asm volatile("red.global.add.v4.f32 [%0], {%1, %2, %3, %4};"
                 :: "l"(p), "f"(m.x), "f"(m.y), "f"(m.z), "f"(m.w)
                 : "memory");
}

// out = (out + y) * scale   (scale = 1 for layers 0,1; 0.25 folded into layer 2)
__global__ void acc_kernel(float* __restrict__ out,
                           const float* __restrict__ y,
                           float scale) {
    size_t i = (size_t)blockIdx.x * blockDim.x + threadIdx.x;
    const size_t total4 = (size_t)N_NODES * DIM / 4;
    if (i >= total4) return;
    float4 o = ((float4*)out)[i];
    float4 v = ((const float4*)y)[i];
    o.x = (o.x + v.x) * scale;
    o.y = (o.y + v.y) * scale;
    o.z = (o.z + v.z) * scale;
    o.w = (o.w + v.w) * scale;
    ((float4*)out)[i] = o;
}

extern "C" void kernel_launch(void* const* d_in, const int* in_sizes, int n_in,
                              void* d_out, int out_size) {
    const float* user_emb = (const float*)d_in[0];
    const float* item_emb = (const float*)d_in[1];
    const float* evals    = (const float*)d_in[2];
    const int*   esrc     = (const int*)  d_in[3];
    const int*   edst     = (const int*)  d_in[4];
    float* out = (float*)d_out;

    float *x, *y;
    cudaGetSymbolAddress((void**)&x, g_bufA);
    cudaGetSymbolAddress((void**)&y, g_bufB);

    const size_t total   = (size_t)N_NODES * DIM;          // 16M floats
    const size_t total4  = total / 4;                      // 4M float4
    const int    TB      = 256;
    const int    g_node  = (int)((total4 + TB - 1) / TB);
    const size_t spmm_th = (size_t)N_EDGES * 16;           // 64M threads
    const int    g_spmm  = (int)((spmm_th + TB - 1) / TB);

    init_kernel<<<g_node, TB>>>(user_emb, item_emb, out, x);

    for (int layer = 0; layer < 3; ++layer) {
        cudaMemsetAsync(y, 0, total * sizeof(float));
        spmm_kernel<<<g_spmm, TB>>>(esrc, edst, evals, x, y);
        float scale = (layer == 2) ? 0.25f : 1.0f;
        acc_kernel<<<g_node, TB>>>(out, y, scale);
        float* tmp = x; x = y; y = tmp;
    }
}

// round 2
// speedup vs baseline: 1.0181x; 1.0181x over previous
#include <cuda_runtime.h>
#include <cstdint>

#define N_USERS 100000
#define N_ITEMS 150000
#define N_NODES (N_USERS + N_ITEMS)
#define N_EDGES 4000000
#define DIM 64

// Per-layer output buffers (64 MB each). x1=layer1, x2=layer2, x3=layer3.
__device__ float g_buf1[(size_t)N_NODES * DIM];
__device__ float g_buf2[(size_t)N_NODES * DIM];
__device__ float g_buf3[(size_t)N_NODES * DIM];

// Zero all three scratch buffers (atomic targets must start at 0).
__global__ void zero_kernel(float* __restrict__ a,
                            float* __restrict__ b,
                            float* __restrict__ c) {
    size_t i = (size_t)blockIdx.x * blockDim.x + threadIdx.x;
    const size_t total4 = (size_t)N_NODES * DIM / 4;
    if (i >= total4) return;
    float4 z = make_float4(0.f, 0.f, 0.f, 0.f);
    ((float4*)a)[i] = z;
    ((float4*)b)[i] = z;
    ((float4*)c)[i] = z;
}

// One half-dimension SpMM pass: y[dst, half] += w * x[src, half].
// 8 threads per edge, each thread owns one float4 of the 32-float half-row.
// A half-row is exactly one 128B L2 line, so each pass's working set is
// 32MB (x) + 32MB (y) and stays L2-resident. Edge arrays are streamed with
// __ldcs (evict-first) so they don't thrash the resident rows.
// Layer 0 gathers straight from the two input tensors via the boundary split;
// later layers pass boundary=N_NODES so the first branch always wins.
__global__ void __launch_bounds__(256) spmm_half_kernel(
    const int*   __restrict__ esrc,
    const int*   __restrict__ edst,
    const float* __restrict__ evals,
    const float* __restrict__ xU,      // rows [0, boundary)
    const float* __restrict__ xI,      // rows [boundary, N_NODES)
    int boundary,
    float*       __restrict__ y,
    int half4)                         // float4 column offset: 0 or 8
{
    size_t t = (size_t)blockIdx.x * blockDim.x + threadIdx.x;
    size_t e = t >> 3;                 // edge index
    if (e >= (size_t)N_EDGES) return;
    int c = (int)(t & 7) + half4;      // float4 chunk within 64-dim row

    int   s = __ldcs(esrc + e);
    int   d = __ldcs(edst + e);
    float w = __ldcs(evals + e);

    const float* xb;
    long si;
    if (s < boundary) { xb = xU; si = s; }
    else              { xb = xI; si = s - boundary; }

    float4 v = __ldg(((const float4*)(xb + (size_t)si * DIM)) + c);
    float4 m;
    m.x = w * v.x; m.y = w * v.y; m.z = w * v.z; m.w = w * v.w;

    float* p = y + (size_t)d * DIM + (size_t)c * 4;
    asm volatile("red.global.add.v4.f32 [%0], {%1, %2, %3, %4};"
                 :: "l"(p), "f"(m.x), "f"(m.y), "f"(m.z), "f"(m.w)
                 : "memory");
}

// out = (concat(user,item) + x1 + x2 + x3) * 0.25
__global__ void final_kernel(const float* __restrict__ user_emb,
                             const float* __restrict__ item_emb,
                             const float* __restrict__ x1,
                             const float* __restrict__ x2,
                             const float* __restrict__ x3,
                             float* __restrict__ out) {
    size_t i = (size_t)blockIdx.x * blockDim.x + threadIdx.x;
    const size_t total4 = (size_t)N_NODES * DIM / 4;
    if (i >= total4) return;
    const size_t ub4 = (size_t)N_USERS * DIM / 4;
    float4 e0;
    if (i < ub4) e0 = __ldcs(((const float4*)user_emb) + i);
    else         e0 = __ldcs(((const float4*)item_emb) + (i - ub4));
    float4 a = __ldcs(((const float4*)x1) + i);
    float4 b = __ldcs(((const float4*)x2) + i);
    float4 cc = __ldcs(((const float4*)x3) + i);
    float4 o;
    o.x = (e0.x + a.x + b.x + cc.x) * 0.25f;
    o.y = (e0.y + a.y + b.y + cc.y) * 0.25f;
    o.z = (e0.z + a.z + b.z + cc.z) * 0.25f;
    o.w = (e0.w + a.w + b.w + cc.w) * 0.25f;
    ((float4*)out)[i] = o;
}

extern "C" void kernel_launch(void* const* d_in, const int* in_sizes, int n_in,
                              void* d_out, int out_size) {
    const float* user_emb = (const float*)d_in[0];
    const float* item_emb = (const float*)d_in[1];
    const float* evals    = (const float*)d_in[2];
    const int*   esrc     = (const int*)  d_in[3];
    const int*   edst     = (const int*)  d_in[4];
    float* out = (float*)d_out;

    float *x1, *x2, *x3;
    cudaGetSymbolAddress((void**)&x1, g_buf1);
    cudaGetSymbolAddress((void**)&x2, g_buf2);
    cudaGetSymbolAddress((void**)&x3, g_buf3);

    const size_t total4 = (size_t)N_NODES * DIM / 4;     // 4M float4
    const int    TB     = 256;
    const int    g_node = (int)((total4 + TB - 1) / TB);
    const size_t spmm_t = (size_t)N_EDGES * 8;           // 32M threads/pass
    const int    g_spmm = (int)((spmm_t + TB - 1) / TB);

    zero_kernel<<<g_node, TB>>>(x1, x2, x3);

    // Layer 1: gather directly from the split input tensors.
    spmm_half_kernel<<<g_spmm, TB>>>(esrc, edst, evals, user_emb, item_emb,
                                     N_USERS, x1, 0);
    spmm_half_kernel<<<g_spmm, TB>>>(esrc, edst, evals, user_emb, item_emb,
                                     N_USERS, x1, 8);
    // Layer 2: x1 -> x2
    spmm_half_kernel<<<g_spmm, TB>>>(esrc, edst, evals, x1, x1,
                                     N_NODES, x2, 0);
    spmm_half_kernel<<<g_spmm, TB>>>(esrc, edst, evals, x1, x1,
                                     N_NODES, x2, 8);
    // Layer 3: x2 -> x3
    spmm_half_kernel<<<g_spmm, TB>>>(esrc, edst, evals, x2, x2,
                                     N_NODES, x3, 0);
    spmm_half_kernel<<<g_spmm, TB>>>(esrc, edst, evals, x2, x2,
                                     N_NODES, x3, 8);

    final_kernel<<<g_node, TB>>>(user_emb, item_emb, x1, x2, x3, out);
}

// round 3
// speedup vs baseline: 1.6752x; 1.6453x over previous
#include <cuda_runtime.h>
#include <cstdint>

#define N_USERS 100000
#define N_ITEMS 150000
#define N_NODES (N_USERS + N_ITEMS)
#define N_EDGES 4000000
#define DIM 64

#define SCAN_TB   256
#define SCAN_IPT  4
#define SCAN_TILE (SCAN_TB * SCAN_IPT)                    // 1024
#define N_SCAN_BLOCKS ((N_NODES + SCAN_TILE - 1) / SCAN_TILE)  // 245

// Layer outputs (64 MB each)
__device__ float g_x1[(size_t)N_NODES * DIM];
__device__ float g_x2[(size_t)N_NODES * DIM];
__device__ float g_x3[(size_t)N_NODES * DIM];
// CSR machinery
__device__ int  g_cnt[N_NODES];
__device__ int  g_rp[N_NODES + 1];
__device__ int  g_offs[N_NODES];
__device__ int  g_sums[SCAN_TB];
__device__ int2 g_edges[N_EDGES];          // packed {src, val_bits}, sorted by dst

// ---------- histogram: cnt[dst]++ (compiles to RED, no return) ----------
__global__ void hist_kernel(const int* __restrict__ edst, int* __restrict__ cnt) {
    int i = blockIdx.x * blockDim.x + threadIdx.x;         // edge/4 index
    if (i >= N_EDGES / 4) return;
    int4 d = __ldcs(((const int4*)edst) + i);
    atomicAdd(cnt + d.x, 1);
    atomicAdd(cnt + d.y, 1);
    atomicAdd(cnt + d.z, 1);
    atomicAdd(cnt + d.w, 1);
}

// ---------- exclusive scan, 3 stages ----------
__global__ void scan_blocks(const int* __restrict__ in, int* __restrict__ out,
                            int* __restrict__ sums, int n) {
    __shared__ int wsum[8];
    int tid  = threadIdx.x;
    int base = blockIdx.x * SCAN_TILE + tid * SCAN_IPT;
    int v0 = 0, v1 = 0, v2 = 0, v3 = 0;
    if (base + 3 < n) {
        int4 t = *(const int4*)(in + base);
        v0 = t.x; v1 = t.y; v2 = t.z; v3 = t.w;
    } else {
        if (base     < n) v0 = in[base];
        if (base + 1 < n) v1 = in[base + 1];
        if (base + 2 < n) v2 = in[base + 2];
    }
    int tsum = v0 + v1 + v2 + v3;
    int lane = tid & 31, wid = tid >> 5;
    int inc = tsum;
    #pragma unroll
    for (int o = 1; o < 32; o <<= 1) {
        int t = __shfl_up_sync(0xffffffffu, inc, o);
        if (lane >= o) inc += t;
    }
    if (lane == 31) wsum[wid] = inc;
    __syncthreads();
    if (tid < 8) {
        int w = wsum[tid];
        #pragma unroll
        for (int o = 1; o < 8; o <<= 1) {
            int t = __shfl_up_sync(0xffu, w, o);
            if (tid >= o) w += t;
        }
        wsum[tid] = w;
    }
    __syncthreads();
    int excl = inc - tsum + (wid ? wsum[wid - 1] : 0);
    if (base     < n) out[base]     = excl;
    if (base + 1 < n) out[base + 1] = excl + v0;
    if (base + 2 < n) out[base + 2] = excl + v0 + v1;
    if (base + 3 < n) out[base + 3] = excl + v0 + v1 + v2;
    if (tid == 0) sums[blockIdx.x] = wsum[7];
}

__global__ void scan_sums(int* __restrict__ sums, int nb) {
    __shared__ int wsum[8];
    int tid = threadIdx.x;
    int v = (tid < nb) ? sums[tid] : 0;
    int lane = tid & 31, wid = tid >> 5;
    int inc = v;
    #pragma unroll
    for (int o = 1; o < 32; o <<= 1) {
        int t = __shfl_up_sync(0xffffffffu, inc, o);
        if (lane >= o) inc += t;
    }
    if (lane == 31) wsum[wid] = inc;
    __syncthreads();
    if (tid < 8) {
        int w = wsum[tid];
        #pragma unroll
        for (int o = 1; o < 8; o <<= 1) {
            int t = __shfl_up_sync(0xffu, w, o);
            if (tid >= o) w += t;
        }
        wsum[tid] = w;
    }
    __syncthreads();
    int excl = inc - v + (wid ? wsum[wid - 1] : 0);
    if (tid < nb) sums[tid] = excl;
}

__global__ void scan_add(int* __restrict__ rp, int* __restrict__ offs,
                         const int* __restrict__ sums) {
    int i = blockIdx.x * blockDim.x + threadIdx.x;
    if (i < N_NODES) {
        int v = rp[i] + sums[i >> 10];
        rp[i]   = v;
        offs[i] = v;
    }
    if (i == N_NODES) rp[N_NODES] = N_EDGES;
}

// ---------- scatter edges into dst-sorted packed array ----------
__global__ void scatter_kernel(const int* __restrict__ esrc,
                               const int* __restrict__ edst,
                               const float* __restrict__ ev,
                               int* __restrict__ offs,
                               int2* __restrict__ edges) {
    int i = blockIdx.x * blockDim.x + threadIdx.x;         // edge/4 index
    if (i >= N_EDGES / 4) return;
    int4   s = __ldcs(((const int4*)esrc) + i);
    int4   d = __ldcs(((const int4*)edst) + i);
    float4 w = __ldcs(((const float4*)ev) + i);
    int p0 = atomicAdd(offs + d.x, 1);
    int p1 = atomicAdd(offs + d.y, 1);
    int p2 = atomicAdd(offs + d.z, 1);
    int p3 = atomicAdd(offs + d.w, 1);
    edges[p0] = make_int2(s.x, __float_as_int(w.x));
    edges[p1] = make_int2(s.y, __float_as_int(w.y));
    edges[p2] = make_int2(s.z, __float_as_int(w.z));
    edges[p3] = make_int2(s.w, __float_as_int(w.w));
}

// ---------- gather-only SpMM: one warp per dst node, float2 per lane ----------
__global__ void __launch_bounds__(256) spmm_csr(
    const int2* __restrict__ edges,
    const int*  __restrict__ rp,
    const float* __restrict__ xU,      // rows [0, boundary)
    const float* __restrict__ xI,      // rows [boundary, N_NODES)
    int boundary,
    float* __restrict__ y) {
    int node = (int)((blockIdx.x * blockDim.x + threadIdx.x) >> 5);
    int lane = threadIdx.x & 31;
    if (node >= N_NODES) return;
    int e   = __ldg(rp + node);
    int end = __ldg(rp + node + 1);
    float ax = 0.f, ay = 0.f, bx = 0.f, by = 0.f;
    // 2-way unrolled: two independent gather chains in flight
    for (; e + 1 < end; e += 2) {
        int2 p0 = __ldg(edges + e);
        int2 p1 = __ldg(edges + e + 1);
        int s0 = p0.x, s1 = p1.x;
        const float* b0 = (s0 < boundary) ? xU : (xI - (size_t)boundary * DIM);
        const float* b1 = (s1 < boundary) ? xU : (xI - (size_t)boundary * DIM);
        float2 v0 = __ldg(((const float2*)(b0 + (size_t)s0 * DIM)) + lane);
        float2 v1 = __ldg(((const float2*)(b1 + (size_t)s1 * DIM)) + lane);
        float w0 = __int_as_float(p0.y);
        float w1 = __int_as_float(p1.y);
        ax += w0 * v0.x; ay += w0 * v0.y;
        bx += w1 * v1.x; by += w1 * v1.y;
    }
    if (e < end) {
        int2 p = __ldg(edges + e);
        int s = p.x;
        const float* b = (s < boundary) ? xU : (xI - (size_t)boundary * DIM);
        float2 v = __ldg(((const float2*)(b + (size_t)s * DIM)) + lane);
        float w = __int_as_float(p.y);
        ax += w * v.x; ay += w * v.y;
    }
    float2 o; o.x = ax + bx; o.y = ay + by;
    ((float2*)(y + (size_t)node * DIM))[lane] = o;
}

// ---------- out = (concat(user,item) + x1 + x2 + x3) * 0.25 ----------
__global__ void final_kernel(const float* __restrict__ user_emb,
                             const float* __restrict__ item_emb,
                             const float* __restrict__ x1,
                             const float* __restrict__ x2,
                             const float* __restrict__ x3,
                             float* __restrict__ out) {
    size_t i = (size_t)blockIdx.x * blockDim.x + threadIdx.x;
    const size_t total4 = (size_t)N_NODES * DIM / 4;
    if (i >= total4) return;
    const size_t ub4 = (size_t)N_USERS * DIM / 4;
    float4 e0;
    if (i < ub4) e0 = __ldcs(((const float4*)user_emb) + i);
    else         e0 = __ldcs(((const float4*)item_emb) + (i - ub4));
    float4 a  = __ldcs(((const float4*)x1) + i);
    float4 b  = __ldcs(((const float4*)x2) + i);
    float4 cc = __ldcs(((const float4*)x3) + i);
    float4 o;
    o.x = (e0.x + a.x + b.x + cc.x) * 0.25f;
    o.y = (e0.y + a.y + b.y + cc.y) * 0.25f;
    o.z = (e0.z + a.z + b.z + cc.z) * 0.25f;
    o.w = (e0.w + a.w + b.w + cc.w) * 0.25f;
    ((float4*)out)[i] = o;
}

extern "C" void kernel_launch(void* const* d_in, const int* in_sizes, int n_in,
                              void* d_out, int out_size) {
    const float* user_emb = (const float*)d_in[0];
    const float* item_emb = (const float*)d_in[1];
    const float* evals    = (const float*)d_in[2];
    const int*   esrc     = (const int*)  d_in[3];
    const int*   edst     = (const int*)  d_in[4];
    float* out = (float*)d_out;

    float *x1, *x2, *x3; int *cnt, *rp, *offs, *sums; int2 *edges;
    cudaGetSymbolAddress((void**)&x1,    g_x1);
    cudaGetSymbolAddress((void**)&x2,    g_x2);
    cudaGetSymbolAddress((void**)&x3,    g_x3);
    cudaGetSymbolAddress((void**)&cnt,   g_cnt);
    cudaGetSymbolAddress((void**)&rp,    g_rp);
    cudaGetSymbolAddress((void**)&offs,  g_offs);
    cudaGetSymbolAddress((void**)&sums,  g_sums);
    cudaGetSymbolAddress((void**)&edges, g_edges);

    const int TB = 256;
    const int g_e4   = (N_EDGES / 4 + TB - 1) / TB;
    const int g_node = (N_NODES + 1 + TB - 1) / TB;
    const int g_spmm = (N_NODES * 32 + TB - 1) / TB;
    const int g_fin  = (int)(((size_t)N_NODES * DIM / 4 + TB - 1) / TB);

    // ---- build CSR (counting sort by dst) ----
    cudaMemsetAsync(cnt, 0, N_NODES * sizeof(int));
    hist_kernel<<<g_e4, TB>>>(edst, cnt);
    scan_blocks<<<N_SCAN_BLOCKS, SCAN_TB>>>(cnt, rp, sums, N_NODES);
    scan_sums<<<1, SCAN_TB>>>(sums, N_SCAN_BLOCKS);
    scan_add<<<g_node, TB>>>(rp, offs, sums);
    scatter_kernel<<<g_e4, TB>>>(esrc, edst, evals, offs, edges);

    // ---- 3 gather-only SpMM layers ----
    spmm_csr<<<g_spmm, TB>>>(edges, rp, user_emb, item_emb, N_USERS, x1);
    spmm_csr<<<g_spmm, TB>>>(edges, rp, x1, x1, N_NODES, x2);
    spmm_csr<<<g_spmm, TB>>>(edges, rp, x2, x2, N_NODES, x3);

    // ---- final combine ----
    final_kernel<<<g_fin, TB>>>(user_emb, item_emb, x1, x2, x3, out);
}

// round 4
// speedup vs baseline: 1.9551x; 1.1671x over previous
#include <cuda_runtime.h>
#include <cstdint>

#define N_USERS 100000
#define N_ITEMS 150000
#define N_NODES (N_USERS + N_ITEMS)
#define N_EDGES 4000000
#define DIM 64

#define SCAN_TB   256
#define SCAN_IPT  4
#define SCAN_TILE (SCAN_TB * SCAN_IPT)                    // 1024
#define N_SCAN_BLOCKS ((N_NODES + SCAN_TILE - 1) / SCAN_TILE)  // 245

// Layer outputs (64 MB each)
__device__ float g_x1[(size_t)N_NODES * DIM];
__device__ float g_x2[(size_t)N_NODES * DIM];
__device__ float g_x3[(size_t)N_NODES * DIM];
// CSR machinery
__device__ int  g_cnt[N_NODES];
__device__ int  g_rp[N_NODES + 1];
__device__ int  g_offs[N_NODES];
__device__ int  g_sums[SCAN_TB];
__device__ int2 g_edges[N_EDGES];          // packed {src, val_bits}, sorted by dst

// ---------- histogram: cnt[dst]++ ----------
__global__ void hist_kernel(const int* __restrict__ edst, int* __restrict__ cnt) {
    int i = blockIdx.x * blockDim.x + threadIdx.x;         // edge/4 index
    if (i >= N_EDGES / 4) return;
    int4 d = __ldcs(((const int4*)edst) + i);
    atomicAdd(cnt + d.x, 1);
    atomicAdd(cnt + d.y, 1);
    atomicAdd(cnt + d.z, 1);
    atomicAdd(cnt + d.w, 1);
}

// ---------- exclusive scan, 3 stages ----------
__global__ void scan_blocks(const int* __restrict__ in, int* __restrict__ out,
                            int* __restrict__ sums, int n) {
    __shared__ int wsum[8];
    int tid  = threadIdx.x;
    int base = blockIdx.x * SCAN_TILE + tid * SCAN_IPT;
    int v0 = 0, v1 = 0, v2 = 0, v3 = 0;
    if (base + 3 < n) {
        int4 t = *(const int4*)(in + base);
        v0 = t.x; v1 = t.y; v2 = t.z; v3 = t.w;
    } else {
        if (base     < n) v0 = in[base];
        if (base + 1 < n) v1 = in[base + 1];
        if (base + 2 < n) v2 = in[base + 2];
    }
    int tsum = v0 + v1 + v2 + v3;
    int lane = tid & 31, wid = tid >> 5;
    int inc = tsum;
    #pragma unroll
    for (int o = 1; o < 32; o <<= 1) {
        int t = __shfl_up_sync(0xffffffffu, inc, o);
        if (lane >= o) inc += t;
    }
    if (lane == 31) wsum[wid] = inc;
    __syncthreads();
    if (tid < 8) {
        int w = wsum[tid];
        #pragma unroll
        for (int o = 1; o < 8; o <<= 1) {
            int t = __shfl_up_sync(0xffu, w, o);
            if (tid >= o) w += t;
        }
        wsum[tid] = w;
    }
    __syncthreads();
    int excl = inc - tsum + (wid ? wsum[wid - 1] : 0);
    if (base     < n) out[base]     = excl;
    if (base + 1 < n) out[base + 1] = excl + v0;
    if (base + 2 < n) out[base + 2] = excl + v0 + v1;
    if (base + 3 < n) out[base + 3] = excl + v0 + v1 + v2;
    if (tid == 0) sums[blockIdx.x] = wsum[7];
}

__global__ void scan_sums(int* __restrict__ sums, int nb) {
    __shared__ int wsum[8];
    int tid = threadIdx.x;
    int v = (tid < nb) ? sums[tid] : 0;
    int lane = tid & 31, wid = tid >> 5;
    int inc = v;
    #pragma unroll
    for (int o = 1; o < 32; o <<= 1) {
        int t = __shfl_up_sync(0xffffffffu, inc, o);
        if (lane >= o) inc += t;
    }
    if (lane == 31) wsum[wid] = inc;
    __syncthreads();
    if (tid < 8) {
        int w = wsum[tid];
        #pragma unroll
        for (int o = 1; o < 8; o <<= 1) {
            int t = __shfl_up_sync(0xffu, w, o);
            if (tid >= o) w += t;
        }
        wsum[tid] = w;
    }
    __syncthreads();
    int excl = inc - v + (wid ? wsum[wid - 1] : 0);
    if (tid < nb) sums[tid] = excl;
}

__global__ void scan_add(int* __restrict__ rp, int* __restrict__ offs,
                         const int* __restrict__ sums) {
    int i = blockIdx.x * blockDim.x + threadIdx.x;
    if (i < N_NODES) {
        int v = rp[i] + sums[i >> 10];
        rp[i]   = v;
        offs[i] = v;
    }
    if (i == N_NODES) rp[N_NODES] = N_EDGES;
}

// ---------- scatter edges into dst-sorted packed array ----------
__global__ void scatter_kernel(const int* __restrict__ esrc,
                               const int* __restrict__ edst,
                               const float* __restrict__ ev,
                               int* __restrict__ offs,
                               int2* __restrict__ edges) {
    int i = blockIdx.x * blockDim.x + threadIdx.x;         // edge/4 index
    if (i >= N_EDGES / 4) return;
    int4   s = __ldcs(((const int4*)esrc) + i);
    int4   d = __ldcs(((const int4*)edst) + i);
    float4 w = __ldcs(((const float4*)ev) + i);
    int p0 = atomicAdd(offs + d.x, 1);
    int p1 = atomicAdd(offs + d.y, 1);
    int p2 = atomicAdd(offs + d.z, 1);
    int p3 = atomicAdd(offs + d.w, 1);
    edges[p0] = make_int2(s.x, __float_as_int(w.x));
    edges[p1] = make_int2(s.y, __float_as_int(w.y));
    edges[p2] = make_int2(s.z, __float_as_int(w.z));
    edges[p3] = make_int2(s.w, __float_as_int(w.w));
}

// ---------- gather-only SpMM: one warp per dst node ----------
// 4 independent edge chains in flight; y written with streaming stores so the
// output doesn't evict the L2-resident x rows + edge array (96MB working set).
__global__ void __launch_bounds__(256) spmm_csr(
    const int2* __restrict__ edges,
    const int*  __restrict__ rp,
    const float* __restrict__ xU,      // rows [0, boundary)
    const float* __restrict__ xI,      // rows [boundary, N_NODES)
    int boundary,
    float* __restrict__ y) {
    int node = (int)((blockIdx.x * blockDim.x + threadIdx.x) >> 5);
    int lane = threadIdx.x & 31;
    if (node >= N_NODES) return;
    int e   = __ldg(rp + node);
    int end = __ldg(rp + node + 1);

    float a0x = 0.f, a0y = 0.f, a1x = 0.f, a1y = 0.f;
    float a2x = 0.f, a2y = 0.f, a3x = 0.f, a3y = 0.f;

    const size_t bofs = (size_t)boundary * DIM;

    // 4-way: batch all edge loads, then all gathers (max MLP per warp)
    for (; e + 3 < end; e += 4) {
        int2 p0 = __ldg(edges + e);
        int2 p1 = __ldg(edges + e + 1);
        int2 p2 = __ldg(edges + e + 2);
        int2 p3 = __ldg(edges + e + 3);
        const float* b0 = (p0.x < boundary) ? xU : (xI - bofs);
        const float* b1 = (p1.x < boundary) ? xU : (xI - bofs);
        const float* b2 = (p2.x < boundary) ? xU : (xI - bofs);
        const float* b3 = (p3.x < boundary) ? xU : (xI - bofs);
        float2 v0 = __ldg(((const float2*)(b0 + (size_t)p0.x * DIM)) + lane);
        float2 v1 = __ldg(((const float2*)(b1 + (size_t)p1.x * DIM)) + lane);
        float2 v2 = __ldg(((const float2*)(b2 + (size_t)p2.x * DIM)) + lane);
        float2 v3 = __ldg(((const float2*)(b3 + (size_t)p3.x * DIM)) + lane);
        float w0 = __int_as_float(p0.y);
        float w1 = __int_as_float(p1.y);
        float w2 = __int_as_float(p2.y);
        float w3 = __int_as_float(p3.y);
        a0x += w0 * v0.x; a0y += w0 * v0.y;
        a1x += w1 * v1.x; a1y += w1 * v1.y;
        a2x += w2 * v2.x; a2y += w2 * v2.y;
        a3x += w3 * v3.x; a3y += w3 * v3.y;
    }
    for (; e < end; ++e) {
        int2 p = __ldg(edges + e);
        const float* b = (p.x < boundary) ? xU : (xI - bofs);
        float2 v = __ldg(((const float2*)(b + (size_t)p.x * DIM)) + lane);
        float w = __int_as_float(p.y);
        a0x += w * v.x; a0y += w * v.y;
    }
    float ox = (a0x + a1x) + (a2x + a3x);
    float oy = (a0y + a1y) + (a2y + a3y);
    float* p = y + (size_t)node * DIM + (size_t)lane * 2;
    asm volatile("st.global.cs.v2.f32 [%0], {%1, %2};"
                 :: "l"(p), "f"(ox), "f"(oy) : "memory");
}

// ---------- out = (concat(user,item) + x1 + x2 + x3) * 0.25 ----------
__global__ void final_kernel(const float* __restrict__ user_emb,
                             const float* __restrict__ item_emb,
                             const float* __restrict__ x1,
                             const float* __restrict__ x2,
                             const float* __restrict__ x3,
                             float* __restrict__ out) {
    size_t i = (size_t)blockIdx.x * blockDim.x + threadIdx.x;
    const size_t total4 = (size_t)N_NODES * DIM / 4;
    if (i >= total4) return;
    const size_t ub4 = (size_t)N_USERS * DIM / 4;
    float4 e0;
    if (i < ub4) e0 = __ldcs(((const float4*)user_emb) + i);
    else         e0 = __ldcs(((const float4*)item_emb) + (i - ub4));
    float4 a  = __ldcs(((const float4*)x1) + i);
    float4 b  = __ldcs(((const float4*)x2) + i);
    float4 cc = __ldcs(((const float4*)x3) + i);
    float4 o;
    o.x = (e0.x + a.x + b.x + cc.x) * 0.25f;
    o.y = (e0.y + a.y + b.y + cc.y) * 0.25f;
    o.z = (e0.z + a.z + b.z + cc.z) * 0.25f;
    o.w = (e0.w + a.w + b.w + cc.w) * 0.25f;
    ((float4*)out)[i] = o;
}

extern "C" void kernel_launch(void* const* d_in, const int* in_sizes, int n_in,
                              void* d_out, int out_size) {
    const float* user_emb = (const float*)d_in[0];
    const float* item_emb = (const float*)d_in[1];
    const float* evals    = (const float*)d_in[2];
    const int*   esrc     = (const int*)  d_in[3];
    const int*   edst     = (const int*)  d_in[4];
    float* out = (float*)d_out;

    float *x1, *x2, *x3; int *cnt, *rp, *offs, *sums; int2 *edges;
    cudaGetSymbolAddress((void**)&x1,    g_x1);
    cudaGetSymbolAddress((void**)&x2,    g_x2);
    cudaGetSymbolAddress((void**)&x3,    g_x3);
    cudaGetSymbolAddress((void**)&cnt,   g_cnt);
    cudaGetSymbolAddress((void**)&rp,    g_rp);
    cudaGetSymbolAddress((void**)&offs,  g_offs);
    cudaGetSymbolAddress((void**)&sums,  g_sums);
    cudaGetSymbolAddress((void**)&edges, g_edges);

    const int TB = 256;
    const int g_e4   = (N_EDGES / 4 + TB - 1) / TB;
    const int g_node = (N_NODES + 1 + TB - 1) / TB;
    const int g_spmm = (N_NODES * 32 + TB - 1) / TB;
    const int g_fin  = (int)(((size_t)N_NODES * DIM / 4 + TB - 1) / TB);

    // ---- build CSR (counting sort by dst) ----
    cudaMemsetAsync(cnt, 0, N_NODES * sizeof(int));
    hist_kernel<<<g_e4, TB>>>(edst, cnt);
    scan_blocks<<<N_SCAN_BLOCKS, SCAN_TB>>>(cnt, rp, sums, N_NODES);
    scan_sums<<<1, SCAN_TB>>>(sums, N_SCAN_BLOCKS);
    scan_add<<<g_node, TB>>>(rp, offs, sums);
    scatter_kernel<<<g_e4, TB>>>(esrc, edst, evals, offs, edges);

    // ---- 3 gather-only SpMM layers ----
    spmm_csr<<<g_spmm, TB>>>(edges, rp, user_emb, item_emb, N_USERS, x1);
    spmm_csr<<<g_spmm, TB>>>(edges, rp, x1, x1, N_NODES, x2);
    spmm_csr<<<g_spmm, TB>>>(edges, rp, x2, x2, N_NODES, x3);

    // ---- final combine ----
    final_kernel<<<g_fin, TB>>>(user_emb, item_emb, x1, x2, x3, out);
}